// round 1
// baseline (speedup 1.0000x reference)
#include <cuda_runtime.h>
#include <math.h>

#define SEQ    2048
#define DMODEL 1024
#define DKEY   64
#define NBATCH 8

// ---------------- scratch (device globals; zero-initialized at module load) ----
__device__ float g_Q[NBATCH * SEQ * DKEY];              //  4 MB
__device__ float g_K[NBATCH * SEQ * DKEY];              //  4 MB
__device__ float g_V[NBATCH * SEQ * DMODEL];            // 64 MB
__device__ float g_P[NBATCH * SEQ * SEQ];               // 128 MB (upper triangle never written -> stays 0)
__device__ float g_Linv[NBATCH * SEQ];

// ---------------------------------------------------------------------------
// Generic tiled SGEMM: C[M,N] = A[M,K] @ B[K,N] (+bias per col) (*rowscale per row)
// BM=128, BN=64, BK=16, 256 threads, 8x4 microtile per thread.
// causal!=0 => k-range limited to (rowblock+1)*128 (used for P@V with causal P).
// Batched via blockIdx.z with strides sA/sB/sC/sR.
// ---------------------------------------------------------------------------
__global__ __launch_bounds__(256)
void gemm_k(const float* __restrict__ A, const float* __restrict__ B,
            float* __restrict__ C, const float* __restrict__ bias,
            const float* __restrict__ rowscale,
            int M, int N, int K, int causal,
            size_t sA, size_t sB, size_t sC, size_t sR)
{
    __shared__ float As[16][128];
    __shared__ float Bs[16][64];

    A += (size_t)blockIdx.z * sA;
    B += (size_t)blockIdx.z * sB;
    C += (size_t)blockIdx.z * sC;
    if (rowscale) rowscale += (size_t)blockIdx.z * sR;

    const int tid = threadIdx.x;
    const int rb = blockIdx.y, cb = blockIdx.x;
    const int r0 = (tid >> 4) << 3;   // 0..120
    const int c0 = (tid & 15) << 2;   // 0..60

    int kend = causal ? (rb + 1) * 128 : K;
    if (kend > K) kend = K;

    const float* Ab = A + (size_t)rb * 128 * K;
    const float* Bb = B + (size_t)cb * 64;

    float acc[8][4];
    #pragma unroll
    for (int i = 0; i < 8; i++)
        #pragma unroll
        for (int j = 0; j < 4; j++) acc[i][j] = 0.f;

    const int la_m = tid >> 2;          // 0..63 (it adds 64)
    const int la_k = (tid & 3) << 2;    // 0,4,8,12
    const int lb_k = tid >> 4;          // 0..15
    const int lb_c = (tid & 15) << 2;   // 0..60

    for (int k0 = 0; k0 < kend; k0 += 16) {
        #pragma unroll
        for (int it = 0; it < 2; it++) {
            int m = la_m + it * 64;
            float4 v = *reinterpret_cast<const float4*>(Ab + (size_t)m * K + k0 + la_k);
            As[la_k + 0][m] = v.x; As[la_k + 1][m] = v.y;
            As[la_k + 2][m] = v.z; As[la_k + 3][m] = v.w;
        }
        *reinterpret_cast<float4*>(&Bs[lb_k][lb_c]) =
            *reinterpret_cast<const float4*>(Bb + (size_t)(k0 + lb_k) * N + lb_c);
        __syncthreads();

        #pragma unroll
        for (int kk = 0; kk < 16; kk++) {
            float4 a0 = *reinterpret_cast<const float4*>(&As[kk][r0]);
            float4 a1 = *reinterpret_cast<const float4*>(&As[kk][r0 + 4]);
            float4 b4 = *reinterpret_cast<const float4*>(&Bs[kk][c0]);
            float aa[8] = {a0.x, a0.y, a0.z, a0.w, a1.x, a1.y, a1.z, a1.w};
            float bb[4] = {b4.x, b4.y, b4.z, b4.w};
            #pragma unroll
            for (int i = 0; i < 8; i++)
                #pragma unroll
                for (int j = 0; j < 4; j++)
                    acc[i][j] = fmaf(aa[i], bb[j], acc[i][j]);
        }
        __syncthreads();
    }

    float bv4[4] = {0.f, 0.f, 0.f, 0.f};
    if (bias) {
        #pragma unroll
        for (int j = 0; j < 4; j++) bv4[j] = bias[cb * 64 + c0 + j];
    }
    #pragma unroll
    for (int i = 0; i < 8; i++) {
        int row = rb * 128 + r0 + i;
        float s = rowscale ? rowscale[row] : 1.0f;
        float4 o;
        o.x = acc[i][0] * s + bv4[0];
        o.y = acc[i][1] * s + bv4[1];
        o.z = acc[i][2] * s + bv4[2];
        o.w = acc[i][3] * s + bv4[3];
        *reinterpret_cast<float4*>(C + (size_t)row * N + cb * 64 + c0) = o;
    }
}

// ---------------------------------------------------------------------------
// Causal scores + softmax numerator: per (batch, 64-row q-block).
// Pass 1: row max over all valid keys.  Pass 2: P = exp(s-m), row sums -> Linv.
// Q pre-scaled by 1/sqrt(DKEY). Scores recomputed (cheap: dk=64).
// ---------------------------------------------------------------------------
__global__ __launch_bounds__(256)
void attn_softmax_k(const float* __restrict__ Qg, const float* __restrict__ Kg,
                    float* __restrict__ Pg, float* __restrict__ Linv)
{
    __shared__ float Qs[64][64];    // [d][r]
    __shared__ float Ks[64][64];    // [d][c]
    __shared__ float red[64][16];
    __shared__ float mrow[64];

    const int tid = threadIdx.x;
    const int qb = blockIdx.x;      // 0..31
    const int b  = blockIdx.y;      // 0..7
    const int r0 = (tid >> 4) << 2; // 0..60
    const int c0 = (tid & 15) << 2; // 0..60

    const float* Qb = Qg + ((size_t)b * SEQ + (size_t)qb * 64) * DKEY;
    const float* Kb = Kg + (size_t)b * SEQ * DKEY;
    float* Pb = Pg + (size_t)b * SEQ * SEQ;

    // load Q tile, transposed to [d][r], pre-scaled by 1/8
    #pragma unroll
    for (int it = 0; it < 4; it++) {
        int f = tid + it * 256;
        int r = f >> 4, d = (f & 15) << 2;
        float4 v = *reinterpret_cast<const float4*>(Qb + (size_t)r * DKEY + d);
        Qs[d + 0][r] = v.x * 0.125f; Qs[d + 1][r] = v.y * 0.125f;
        Qs[d + 2][r] = v.z * 0.125f; Qs[d + 3][r] = v.w * 0.125f;
    }

    // ---------------- pass 1: row max ----------------
    float rmax[4] = {-1e30f, -1e30f, -1e30f, -1e30f};
    for (int j = 0; j <= qb; j++) {
        __syncthreads();
        #pragma unroll
        for (int it = 0; it < 4; it++) {
            int f = tid + it * 256;
            int c = f >> 4, d = (f & 15) << 2;
            float4 v = *reinterpret_cast<const float4*>(Kb + ((size_t)(j * 64 + c)) * DKEY + d);
            Ks[d + 0][c] = v.x; Ks[d + 1][c] = v.y;
            Ks[d + 2][c] = v.z; Ks[d + 3][c] = v.w;
        }
        __syncthreads();

        float acc[4][4];
        #pragma unroll
        for (int i = 0; i < 4; i++)
            #pragma unroll
            for (int jj = 0; jj < 4; jj++) acc[i][jj] = 0.f;
        #pragma unroll 8
        for (int d = 0; d < 64; d++) {
            float4 q4 = *reinterpret_cast<const float4*>(&Qs[d][r0]);
            float4 k4 = *reinterpret_cast<const float4*>(&Ks[d][c0]);
            float qa[4] = {q4.x, q4.y, q4.z, q4.w};
            float ka[4] = {k4.x, k4.y, k4.z, k4.w};
            #pragma unroll
            for (int i = 0; i < 4; i++)
                #pragma unroll
                for (int jj = 0; jj < 4; jj++)
                    acc[i][jj] = fmaf(qa[i], ka[jj], acc[i][jj]);
        }
        const bool diag = (j == qb);
        #pragma unroll
        for (int i = 0; i < 4; i++) {
            int grow = r0 + i;
            #pragma unroll
            for (int jj = 0; jj < 4; jj++) {
                bool ok = !diag || ((c0 + jj) <= grow);
                if (ok) rmax[i] = fmaxf(rmax[i], acc[i][jj]);
            }
        }
    }
    __syncthreads();
    #pragma unroll
    for (int i = 0; i < 4; i++) red[r0 + i][tid & 15] = rmax[i];
    __syncthreads();
    if (tid < 64) {
        float m = red[tid][0];
        #pragma unroll
        for (int t = 1; t < 16; t++) m = fmaxf(m, red[tid][t]);
        mrow[tid] = m;
    }
    __syncthreads();
    float mr[4];
    #pragma unroll
    for (int i = 0; i < 4; i++) mr[i] = mrow[r0 + i];

    // ---------------- pass 2: numerators + row sums ----------------
    float lsum[4] = {0.f, 0.f, 0.f, 0.f};
    for (int j = 0; j <= qb; j++) {
        __syncthreads();
        #pragma unroll
        for (int it = 0; it < 4; it++) {
            int f = tid + it * 256;
            int c = f >> 4, d = (f & 15) << 2;
            float4 v = *reinterpret_cast<const float4*>(Kb + ((size_t)(j * 64 + c)) * DKEY + d);
            Ks[d + 0][c] = v.x; Ks[d + 1][c] = v.y;
            Ks[d + 2][c] = v.z; Ks[d + 3][c] = v.w;
        }
        __syncthreads();

        float acc[4][4];
        #pragma unroll
        for (int i = 0; i < 4; i++)
            #pragma unroll
            for (int jj = 0; jj < 4; jj++) acc[i][jj] = 0.f;
        #pragma unroll 8
        for (int d = 0; d < 64; d++) {
            float4 q4 = *reinterpret_cast<const float4*>(&Qs[d][r0]);
            float4 k4 = *reinterpret_cast<const float4*>(&Ks[d][c0]);
            float qa[4] = {q4.x, q4.y, q4.z, q4.w};
            float ka[4] = {k4.x, k4.y, k4.z, k4.w};
            #pragma unroll
            for (int i = 0; i < 4; i++)
                #pragma unroll
                for (int jj = 0; jj < 4; jj++)
                    acc[i][jj] = fmaf(qa[i], ka[jj], acc[i][jj]);
        }
        const bool diag = (j == qb);
        #pragma unroll
        for (int i = 0; i < 4; i++) {
            int grow = r0 + i;
            float ev[4];
            #pragma unroll
            for (int jj = 0; jj < 4; jj++) {
                bool ok = !diag || ((c0 + jj) <= grow);
                float x = ok ? __expf(acc[i][jj] - mr[i]) : 0.f;
                ev[jj] = x;
                lsum[i] += x;
            }
            float4 o = {ev[0], ev[1], ev[2], ev[3]};
            *reinterpret_cast<float4*>(Pb + ((size_t)(qb * 64 + grow)) * SEQ + j * 64 + c0) = o;
        }
    }
    __syncthreads();
    #pragma unroll
    for (int i = 0; i < 4; i++) red[r0 + i][tid & 15] = lsum[i];
    __syncthreads();
    if (tid < 64) {
        float l = 0.f;
        #pragma unroll
        for (int t = 0; t < 16; t++) l += red[tid][t];
        Linv[(size_t)b * SEQ + qb * 64 + tid] = 1.0f / l;
    }
}

// ---------------------------------------------------------------------------
extern "C" void kernel_launch(void* const* d_in, const int* in_sizes, int n_in,
                              void* d_out, int out_size)
{
    const float* input = (const float*)d_in[0];
    const float* Wq = (const float*)d_in[1];
    const float* bq = (const float*)d_in[2];
    const float* Wk = (const float*)d_in[3];
    const float* bk = (const float*)d_in[4];
    const float* Wv = (const float*)d_in[5];
    const float* bv = (const float*)d_in[6];
    float* out = (float*)d_out;

    float *Qp, *Kp, *Vp, *Pp, *Lp;
    cudaGetSymbolAddress((void**)&Qp, g_Q);
    cudaGetSymbolAddress((void**)&Kp, g_K);
    cudaGetSymbolAddress((void**)&Vp, g_V);
    cudaGetSymbolAddress((void**)&Pp, g_P);
    cudaGetSymbolAddress((void**)&Lp, g_Linv);

    dim3 blk(256);
    const int Mrows = NBATCH * SEQ;   // 16384

    // Q = input @ Wq + bq   [16384, 64]
    gemm_k<<<dim3(DKEY / 64, Mrows / 128, 1), blk>>>(
        input, Wq, Qp, bq, nullptr, Mrows, DKEY, DMODEL, 0, 0, 0, 0, 0);
    // K = input @ Wk + bk
    gemm_k<<<dim3(DKEY / 64, Mrows / 128, 1), blk>>>(
        input, Wk, Kp, bk, nullptr, Mrows, DKEY, DMODEL, 0, 0, 0, 0, 0);
    // V = input @ Wv + bv   [16384, 1024]
    gemm_k<<<dim3(DMODEL / 64, Mrows / 128, 1), blk>>>(
        input, Wv, Vp, bv, nullptr, Mrows, DMODEL, DMODEL, 0, 0, 0, 0, 0);

    // P (unnormalized softmax numerators, causal) + Linv
    attn_softmax_k<<<dim3(SEQ / 64, NBATCH), blk>>>(Qp, Kp, Pp, Lp);

    // out = diag(Linv) * P @ V   (batched, causal k-limit)
    gemm_k<<<dim3(DMODEL / 64, SEQ / 128, NBATCH), blk>>>(
        Pp, Vp, out, nullptr, Lp, SEQ, DMODEL, SEQ, 1,
        (size_t)SEQ * SEQ, (size_t)SEQ * DMODEL, (size_t)SEQ * DMODEL, (size_t)SEQ);
}

// round 4
// speedup vs baseline: 2.8462x; 2.8462x over previous
#include <cuda_runtime.h>
#include <cstdint>

#define SEQ 2048
#define DM  1024
#define DK  64
#define NB  8

// ------------------------- scratch (device globals) -------------------------
__device__ float g_Q[NB * SEQ * DK];                 //  4 MB
__device__ float g_K[NB * SEQ * DK];                 //  4 MB
__device__ float g_V[NB * SEQ * DM];                 // 64 MB
__device__ float g_S[(size_t)NB * SEQ * SEQ];        // 128 MB (scores -> P in place)
__device__ float g_Linv[NB * SEQ];

// ------------------------- helpers -------------------------
__device__ __forceinline__ uint32_t f2tf(float f) {
    uint32_t o;
    asm("cvt.rna.tf32.f32 %0, %1;" : "=r"(o) : "f"(f));
    return o;
}
__device__ __forceinline__ void mma_tf32(float* c, const uint32_t* a, const uint32_t* b) {
    asm volatile(
        "mma.sync.aligned.m16n8k8.row.col.f32.tf32.tf32.f32 "
        "{%0,%1,%2,%3}, {%4,%5,%6,%7}, {%8,%9}, {%0,%1,%2,%3};"
        : "+f"(c[0]), "+f"(c[1]), "+f"(c[2]), "+f"(c[3])
        : "r"(a[0]), "r"(a[1]), "r"(a[2]), "r"(a[3]), "r"(b[0]), "r"(b[1]));
}

#define AS_STR 20    // 16 + 4 pad: fragment LDS conflict-free
#define BS_STR 136   // 128 + 8 pad: k-stride = 8 banks -> conflict-free frag LDS

// ---------------------------------------------------------------------------
// tf32 mma.sync GEMM.
//   A: [M,K] row-major.
//   B: transB=0 -> [K,N] row-major;  transB=1 -> [N,K] row-major (B^T effective).
//   C[128-tile] = rowscale * (A @ B) + bias.
//   causalK: K limited to (rb+1)*128.  causalSkip: skip block cols above diag.
//   Batched via blockIdx.z with strides.
// ---------------------------------------------------------------------------
__global__ __launch_bounds__(256)
void mma_gemm(const float* __restrict__ A, const float* __restrict__ B,
              float* __restrict__ C, const float* __restrict__ bias,
              const float* __restrict__ rowscale,
              int N, int K, int transB, int causalK, int causalSkip,
              size_t sA, size_t sB, size_t sC, size_t sR)
{
    __shared__ uint32_t As[2][128 * AS_STR];
    __shared__ uint32_t Bs[2][16 * BS_STR];

    const int rb = blockIdx.y, cb = blockIdx.x, z = blockIdx.z;
    if (causalSkip && cb > rb) return;

    A += (size_t)z * sA;
    B += (size_t)z * sB;
    C += (size_t)z * sC;
    if (rowscale) rowscale += (size_t)z * sR;

    int kend = causalK ? (rb + 1) * 128 : K;
    if (kend > K) kend = K;
    const int NC = kend >> 4;

    const int tid = threadIdx.x, lane = tid & 31;
    const int wm = (tid >> 5) >> 1;      // 0..3
    const int wn = (tid >> 5) & 1;       // 0..1

    const float* Ab = A + (size_t)rb * 128 * K;

    float acc[2][8][4];
    #pragma unroll
    for (int i = 0; i < 2; i++)
        #pragma unroll
        for (int j = 0; j < 8; j++)
            #pragma unroll
            for (int q = 0; q < 4; q++) acc[i][j][q] = 0.f;

    float4 la[2], lb[2];

    auto gload = [&](int c) {
        const float* Ac = Ab + (c << 4);
        #pragma unroll
        for (int it = 0; it < 2; it++) {
            int f = tid + it * 256;
            la[it] = *reinterpret_cast<const float4*>(
                Ac + (size_t)(f >> 2) * K + ((f & 3) << 2));
        }
        if (!transB) {
            const float* Bc = B + (size_t)(c << 4) * N + cb * 128;
            #pragma unroll
            for (int it = 0; it < 2; it++) {
                int f = tid + it * 256;
                int kr = f >> 5, nc = (f & 31) << 2;
                if (cb * 128 + nc < N)
                    lb[it] = *reinterpret_cast<const float4*>(Bc + (size_t)kr * N + nc);
                else
                    lb[it] = make_float4(0.f, 0.f, 0.f, 0.f);
            }
        } else {
            const float* Bc = B + (size_t)(cb * 128) * K + (c << 4);
            #pragma unroll
            for (int it = 0; it < 2; it++) {
                int f = tid + it * 256;
                lb[it] = *reinterpret_cast<const float4*>(
                    Bc + (size_t)(f >> 2) * K + ((f & 3) << 2));
            }
        }
    };

    auto gstore = [&](int buf) {
        #pragma unroll
        for (int it = 0; it < 2; it++) {
            int f = tid + it * 256;
            int row = f >> 2, kc = (f & 3) << 2;
            uint32_t* p = &As[buf][row * AS_STR + kc];
            p[0] = f2tf(la[it].x); p[1] = f2tf(la[it].y);
            p[2] = f2tf(la[it].z); p[3] = f2tf(la[it].w);
        }
        if (!transB) {
            #pragma unroll
            for (int it = 0; it < 2; it++) {
                int f = tid + it * 256;
                int kr = f >> 5, nc = (f & 31) << 2;
                uint32_t* p = &Bs[buf][kr * BS_STR + nc];
                p[0] = f2tf(lb[it].x); p[1] = f2tf(lb[it].y);
                p[2] = f2tf(lb[it].z); p[3] = f2tf(lb[it].w);
            }
        } else {
            #pragma unroll
            for (int it = 0; it < 2; it++) {
                int f = tid + it * 256;
                int nr = f >> 2, kc = (f & 3) << 2;
                Bs[buf][(kc + 0) * BS_STR + nr] = f2tf(lb[it].x);
                Bs[buf][(kc + 1) * BS_STR + nr] = f2tf(lb[it].y);
                Bs[buf][(kc + 2) * BS_STR + nr] = f2tf(lb[it].z);
                Bs[buf][(kc + 3) * BS_STR + nr] = f2tf(lb[it].w);
            }
        }
    };

    auto compute = [&](int buf) {
        #pragma unroll
        for (int ks = 0; ks < 2; ks++) {
            const int kk = ks * 8;
            uint32_t a[2][4], b[8][2];
            #pragma unroll
            for (int mi = 0; mi < 2; mi++) {
                int m = wm * 32 + mi * 16 + (lane >> 2);
                a[mi][0] = As[buf][m * AS_STR + kk + (lane & 3)];
                a[mi][1] = As[buf][(m + 8) * AS_STR + kk + (lane & 3)];
                a[mi][2] = As[buf][m * AS_STR + kk + 4 + (lane & 3)];
                a[mi][3] = As[buf][(m + 8) * AS_STR + kk + 4 + (lane & 3)];
            }
            #pragma unroll
            for (int ni = 0; ni < 8; ni++) {
                int n = wn * 64 + ni * 8 + (lane >> 2);
                b[ni][0] = Bs[buf][(kk + (lane & 3)) * BS_STR + n];
                b[ni][1] = Bs[buf][(kk + 4 + (lane & 3)) * BS_STR + n];
            }
            #pragma unroll
            for (int mi = 0; mi < 2; mi++)
                #pragma unroll
                for (int ni = 0; ni < 8; ni++)
                    mma_tf32(acc[mi][ni], a[mi], b[ni]);
        }
    };

    gload(0);
    gstore(0);
    __syncthreads();
    for (int c = 0; c < NC; c++) {
        const int buf = c & 1;
        if (c + 1 < NC) gload(c + 1);
        compute(buf);
        if (c + 1 < NC) gstore(buf ^ 1);
        __syncthreads();
    }

    // ---------------- epilogue ----------------
    #pragma unroll
    for (int mi = 0; mi < 2; mi++) {
        int rbase = rb * 128 + wm * 32 + mi * 16 + (lane >> 2);
        #pragma unroll
        for (int half = 0; half < 2; half++) {
            int row = rbase + half * 8;
            float sc = rowscale ? rowscale[row] : 1.0f;
            float* Cp = C + (size_t)row * N;
            #pragma unroll
            for (int ni = 0; ni < 8; ni++) {
                int col = cb * 128 + wn * 64 + ni * 8 + ((lane & 3) << 1);
                if (col < N) {
                    float b0 = 0.f, b1 = 0.f;
                    if (bias) { b0 = bias[col]; b1 = bias[col + 1]; }
                    float2 o;
                    o.x = acc[mi][ni][half * 2 + 0] * sc + b0;
                    o.y = acc[mi][ni][half * 2 + 1] * sc + b1;
                    *reinterpret_cast<float2*>(Cp + col) = o;
                }
            }
        }
    }
}

// ---------------------------------------------------------------------------
// Rowwise causal softmax, in-place on S -> P. Writes Linv = 1/rowsum.
// Zero-fills cols [q+1, roundup(q+1,128)) so PV's 128-granular causal
// K-limit reads exact zeros above the diagonal.
// ---------------------------------------------------------------------------
__global__ __launch_bounds__(256)
void softmax_rows(float* __restrict__ S, float* __restrict__ Linv)
{
    __shared__ float red[256];
    const int q = blockIdx.x, b = blockIdx.y;
    float* row = S + ((size_t)b * SEQ + q) * SEQ;
    const int n = q + 1;
    const int nk4 = (((q >> 7) + 1) << 7) >> 2;
    const int tid = threadIdx.x;

    float m = -1e30f;
    for (int i = tid; i < nk4; i += 256) {
        float4 v = reinterpret_cast<const float4*>(row)[i];
        int base = i << 2;
        if (base + 0 < n) m = fmaxf(m, v.x);
        if (base + 1 < n) m = fmaxf(m, v.y);
        if (base + 2 < n) m = fmaxf(m, v.z);
        if (base + 3 < n) m = fmaxf(m, v.w);
    }
    red[tid] = m; __syncthreads();
    for (int s2 = 128; s2 > 0; s2 >>= 1) {
        if (tid < s2) red[tid] = fmaxf(red[tid], red[tid + s2]);
        __syncthreads();
    }
    m = red[0] * 0.125f;   // fold 1/sqrt(dk)
    __syncthreads();

    float sum = 0.f;
    for (int i = tid; i < nk4; i += 256) {
        float4 v = reinterpret_cast<const float4*>(row)[i];
        int base = i << 2;
        float4 p;
        p.x = (base + 0 < n) ? __expf(v.x * 0.125f - m) : 0.f;
        p.y = (base + 1 < n) ? __expf(v.y * 0.125f - m) : 0.f;
        p.z = (base + 2 < n) ? __expf(v.z * 0.125f - m) : 0.f;
        p.w = (base + 3 < n) ? __expf(v.w * 0.125f - m) : 0.f;
        sum += p.x + p.y + p.z + p.w;
        reinterpret_cast<float4*>(row)[i] = p;
    }
    red[tid] = sum; __syncthreads();
    for (int s2 = 128; s2 > 0; s2 >>= 1) {
        if (tid < s2) red[tid] += red[tid + s2];
        __syncthreads();
    }
    if (tid == 0) Linv[(size_t)b * SEQ + q] = 1.0f / red[0];
}

// ---------------------------------------------------------------------------
extern "C" void kernel_launch(void* const* d_in, const int* in_sizes, int n_in,
                              void* d_out, int out_size)
{
    const float* input = (const float*)d_in[0];
    const float* Wq = (const float*)d_in[1];
    const float* bq = (const float*)d_in[2];
    const float* Wk = (const float*)d_in[3];
    const float* bk = (const float*)d_in[4];
    const float* Wv = (const float*)d_in[5];
    const float* bv = (const float*)d_in[6];
    float* out = (float*)d_out;

    float *Q, *Kb, *V, *S, *L;
    cudaGetSymbolAddress((void**)&Q,  g_Q);
    cudaGetSymbolAddress((void**)&Kb, g_K);
    cudaGetSymbolAddress((void**)&V,  g_V);
    cudaGetSymbolAddress((void**)&S,  g_S);
    cudaGetSymbolAddress((void**)&L,  g_Linv);

    const int Mrows = NB * SEQ;   // 16384

    // Q = X @ Wq + bq            [16384, 64]     (B row-major [1024,64])
    mma_gemm<<<dim3(1, Mrows / 128, 1), 256>>>(
        input, Wq, Q, bq, nullptr, DK, DM, 0, 0, 0, 0, 0, 0, 0);
    // K = X @ Wk + bk
    mma_gemm<<<dim3(1, Mrows / 128, 1), 256>>>(
        input, Wk, Kb, bk, nullptr, DK, DM, 0, 0, 0, 0, 0, 0, 0);
    // V = X @ Wv + bv            [16384, 1024]
    mma_gemm<<<dim3(DM / 128, Mrows / 128, 1), 256>>>(
        input, Wv, V, bv, nullptr, DM, DM, 0, 0, 0, 0, 0, 0, 0);

    // S = Q @ K^T per batch (transB; blocks above diagonal skipped)
    mma_gemm<<<dim3(SEQ / 128, SEQ / 128, NB), 256>>>(
        Q, Kb, S, nullptr, nullptr, SEQ, DK, 1, 0, 1,
        (size_t)SEQ * DK, (size_t)SEQ * DK, (size_t)SEQ * SEQ, 0);

    // softmax rows: S -> P (in place) + Linv
    softmax_rows<<<dim3(SEQ, NB), 256>>>(S, L);

    // out = diag(Linv) * P @ V   (causal K-limit per 128-row block)
    mma_gemm<<<dim3(DM / 128, SEQ / 128, NB), 256>>>(
        S, V, out, nullptr, L, DM, SEQ, 0, 1, 0,
        (size_t)SEQ * SEQ, (size_t)SEQ * DM, (size_t)SEQ * DM, (size_t)SEQ);
}